// round 6
// baseline (speedup 1.0000x reference)
#include <cuda_runtime.h>
#include <cuda_bf16.h>

typedef unsigned long long u64;
typedef unsigned int u32;

#define E_TOT   10000
#define FREQ    44
#define EB      16
#define NBLK    (E_TOT / EB)      // 625
#define LN_EPS  1e-5f

// scratch
__device__ float g_h[E_TOT * 32];
__device__ float g_w3t2[FREQ * 32 * 256];   // [f][m][co][ci]

// ---------------------------------------------------------------------------
__device__ __forceinline__ u64 f2fma(u64 a, u64 b, u64 c) {
    u64 d;
    asm("fma.rn.f32x2 %0, %1, %2, %3;" : "=l"(d) : "l"(a), "l"(b), "l"(c));
    return d;
}
__device__ __forceinline__ u64 dup2(float x) {
    u64 d;
    asm("mov.b64 %0, {%1, %1};" : "=l"(d) : "f"(x));
    return d;
}
__device__ __forceinline__ u32 smem_u32(const void* p) {
    u32 a;
    asm("{ .reg .u64 t; cvta.to.shared.u64 t, %1; cvt.u32.u64 %0, t; }" : "=r"(a) : "l"(p));
    return a;
}
__device__ __forceinline__ void cp16(u32 s, const float* g) {
    asm volatile("cp.async.cg.shared.global [%0], [%1], 16;\n" :: "r"(s), "l"(g));
}
__device__ __forceinline__ void cp_commit() {
    asm volatile("cp.async.commit_group;\n");
}
template <int N>
__device__ __forceinline__ void cp_wait() {
    asm volatile("cp.async.wait_group %0;\n" :: "n"(N));
}

// ---------------------------------------------------------------------------
// Kernel 0: transpose w3 -> g_w3t2[f][m][co][ci], w3 row = co*704 + ci*44 + f
// ---------------------------------------------------------------------------
__global__ void w3t_kernel(const float* __restrict__ w3) {
    int idx = blockIdx.x * 256 + threadIdx.x;
    if (idx < FREQ * 32 * 256) {
        int ci = idx & 15;
        int co = (idx >> 4) & 15;
        int m  = (idx >> 8) & 31;
        int f  = idx >> 13;
        g_w3t2[idx] = w3[(co * 704 + ci * 44 + f) * 32 + m];
    }
}

// ---------------------------------------------------------------------------
// Kernel 1: RadialProfile MLP
// ---------------------------------------------------------------------------
__device__ __forceinline__ float ln_relu_32(float y, float gamma, float beta) {
    float s = y, q = y * y;
    #pragma unroll
    for (int d = 16; d > 0; d >>= 1) {
        s += __shfl_xor_sync(0xffffffffu, s, d);
        q += __shfl_xor_sync(0xffffffffu, q, d);
    }
    float mean = s * (1.0f / 32.0f);
    float var  = q * (1.0f / 32.0f) - mean * mean;
    float r = rsqrtf(var + LN_EPS);
    float v = (y - mean) * r * gamma + beta;
    return fmaxf(v, 0.0f);
}

__global__ void __launch_bounds__(256) mlp_kernel(
    const float* __restrict__ inv,
    const float* __restrict__ w1, const float* __restrict__ b1,
    const float* __restrict__ g1, const float* __restrict__ be1,
    const float* __restrict__ w2, const float* __restrict__ b2,
    const float* __restrict__ g2, const float* __restrict__ be2)
{
    __shared__ float w1_s[32 * 16];
    __shared__ float w2_s[32 * 32];
    __shared__ float p_s[6 * 32];

    int tid = threadIdx.x;
    for (int i = tid; i < 512;  i += 256) w1_s[i] = w1[i];
    for (int i = tid; i < 1024; i += 256) w2_s[i] = w2[i];
    if (tid < 32) {
        p_s[tid]       = b1[tid];
        p_s[32  + tid] = g1[tid];
        p_s[64  + tid] = be1[tid];
        p_s[96  + tid] = b2[tid];
        p_s[128 + tid] = g2[tid];
        p_s[160 + tid] = be2[tid];
    }
    __syncthreads();

    int w = tid >> 5;
    int m = tid & 31;
    int e = blockIdx.x * 8 + w;

    float xv = (m < 16) ? inv[e * 16 + m] : 0.0f;

    float y = p_s[m];
    #pragma unroll
    for (int in = 0; in < 16; in++)
        y = fmaf(__shfl_sync(0xffffffffu, xv, in), w1_s[m * 16 + in], y);
    y = ln_relu_32(y, p_s[32 + m], p_s[64 + m]);

    float y2 = p_s[96 + m];
    #pragma unroll
    for (int k = 0; k < 32; k++)
        y2 = fmaf(__shfl_sync(0xffffffffu, y, k), w2_s[m * 32 + k], y2);
    y2 = ln_relu_32(y2, p_s[128 + m], p_s[160 + m]);

    g_h[e * 32 + m] = y2;
}

// ---------------------------------------------------------------------------
// Kernel 2: fused conv. EB=16 edges/block, 256 threads, thread = (e, co/ci).
//
// per f:
//   issue cp.async prefetch of basis slice f+1 (double-buffered, 260-pad rows)
//   step3: accR[ci-pair] = sum_m hd[e][m] * W2[f][m][co][ci-pair]   (regs only)
//   wait+bar: basis slice f ready
//   step2: T[e][ci][o] = sum_in feat[in] * bb[e][in][o]  -> Ts[f&1] (chunk-XOR)
//   bar
//   step4: accO[o-pair] += R[ci] * T[e][ci][o-pair]
// ---------------------------------------------------------------------------
#define BB_STRIDE 260
#define BB_FLOATS (EB * BB_STRIDE)           // 4160 per buffer

__global__ void __launch_bounds__(256, 2) conv_main_kernel(
    const float* __restrict__ features,  // [E,16,16]
    const float* __restrict__ basis,     // [E,16,44,16]
    float*       __restrict__ out)       // [E,16,16]
{
    extern __shared__ float sm[];
    float* bb = sm;                      // 2 * 4160 = 8320
    float* Ts = sm + 2 * BB_FLOATS;      // 2 * 4096 = 8192
    float* hd = Ts + 8192;               // 16*33*2  = 1056  -> 17568 floats

    const int t  = threadIdx.x;
    const int e0 = blockIdx.x * EB;
    const int e  = t >> 4;               // edge 0..15
    const int co = t & 15;               // also ci role in step2
    const int ci2 = co;

    // ---- stage hd[e][m] as duplicated u64 pairs ----
    {
        int ee = t >> 4, mm0 = (t & 15) * 2;
        #pragma unroll
        for (int k = 0; k < 2; k++) {
            float v = g_h[(e0 + ee) * 32 + mm0 + k];
            hd[(ee * 33 + mm0 + k) * 2]     = v;
            hd[(ee * 33 + mm0 + k) * 2 + 1] = v;
        }
    }

    // ---- features row (e, ci2) hoisted to regs ----
    float fF[16];
    {
        const float4* fp = reinterpret_cast<const float4*>(features + ((size_t)(e0 + e) * 16 + ci2) * 16);
        #pragma unroll
        for (int k = 0; k < 4; k++) {
            float4 v = fp[k];
            fF[4*k] = v.x; fF[4*k+1] = v.y; fF[4*k+2] = v.z; fF[4*k+3] = v.w;
        }
    }

    // cp.async staging role: row (e, in) -> 64 bytes
    const int cpe  = t >> 4;
    const int cpin = t & 15;
    const float* cp_src_base = basis + (size_t)(e0 + cpe) * 11264 + cpin * 704;
    const u32 cp_dst = smem_u32(bb) + (cpe * BB_STRIDE + cpin * 16) * 4;

    u64 accO[8];
    #pragma unroll
    for (int i = 0; i < 8; i++) accO[i] = 0ull;

    // prefetch f = 0
    {
        const float* g = cp_src_base;            // + f*16, f=0
        #pragma unroll
        for (int q = 0; q < 4; q++) cp16(cp_dst + q * 16, g + q * 4);
        cp_commit();
    }

    const float* w2base = g_w3t2 + co * 16;      // + (f*32+m)*256

    __syncthreads();   // hd ready (and ordering for smem init)

    for (int f = 0; f < FREQ; f++) {
        // ---- issue prefetch of slice f+1 ----
        if (f + 1 < FREQ) {
            const float* g = cp_src_base + (f + 1) * 16;
            u32 d = cp_dst + ((f + 1) & 1) * (BB_FLOATS * 4);
            #pragma unroll
            for (int q = 0; q < 4; q++) cp16(d + q * 16, g + q * 4);
            cp_commit();
        }

        // ---- step3: R[e][ci*16+co] over all ci, in registers ----
        u64 accR[8];
        #pragma unroll
        for (int i = 0; i < 8; i++) accR[i] = 0ull;
        {
            const float* wp = w2base + (size_t)(f * 32) * 256;
            const float* hp = hd + e * 66;
            #pragma unroll 8
            for (int m = 0; m < 32; m++) {
                u64 hv = *reinterpret_cast<const u64*>(hp + m * 2);
                const ulonglong2* wq = reinterpret_cast<const ulonglong2*>(wp + m * 256);
                ulonglong2 w0 = wq[0], w1 = wq[1], w2v = wq[2], w3v = wq[3];
                accR[0] = f2fma(hv, w0.x, accR[0]);
                accR[1] = f2fma(hv, w0.y, accR[1]);
                accR[2] = f2fma(hv, w1.x, accR[2]);
                accR[3] = f2fma(hv, w1.y, accR[3]);
                accR[4] = f2fma(hv, w2v.x, accR[4]);
                accR[5] = f2fma(hv, w2v.y, accR[5]);
                accR[6] = f2fma(hv, w3v.x, accR[6]);
                accR[7] = f2fma(hv, w3v.y, accR[7]);
            }
        }

        // ---- basis slice f ready for everyone ----
        if (f + 1 < FREQ) cp_wait<1>(); else cp_wait<0>();
        __syncthreads();

        // ---- step2: T[e][ci2][0..15] from bb ----
        {
            u64 tacc[8];
            #pragma unroll
            for (int i = 0; i < 8; i++) tacc[i] = 0ull;
            const float* bp = bb + (f & 1) * BB_FLOATS + e * BB_STRIDE;
            #pragma unroll 4
            for (int in = 0; in < 16; in++) {
                const ulonglong2* q = reinterpret_cast<const ulonglong2*>(bp + in * 16);
                ulonglong2 b0 = q[0], b1 = q[1];
                u64 fd = dup2(fF[in]);
                tacc[0] = f2fma(fd, b0.x, tacc[0]);
                tacc[1] = f2fma(fd, b0.y, tacc[1]);
                tacc[2] = f2fma(fd, b1.x, tacc[2]);
                tacc[3] = f2fma(fd, b1.y, tacc[3]);
            }
            #pragma unroll 4
            for (int in = 0; in < 16; in++) {
                const ulonglong2* q = reinterpret_cast<const ulonglong2*>(bp + in * 16 + 8);
                ulonglong2 b0 = q[0];
                u64 fd = dup2(fF[in]);
                tacc[4] = f2fma(fd, b0.x, tacc[4]);
                tacc[5] = f2fma(fd, b0.y, tacc[5]);
            }
            #pragma unroll 4
            for (int in = 0; in < 16; in++) {
                const ulonglong2* q = reinterpret_cast<const ulonglong2*>(bp + in * 16 + 12);
                ulonglong2 b0 = q[0];
                u64 fd = dup2(fF[in]);
                tacc[6] = f2fma(fd, b0.x, tacc[6]);
                tacc[7] = f2fma(fd, b0.y, tacc[7]);
            }
            // store with chunk-XOR swizzle: kk = k ^ (ci&3) ^ ((e&1)<<1)
            float* tb = Ts + (f & 1) * 4096 + e * 256 + ci2 * 16;
            const int sw = (ci2 & 3) ^ ((e & 1) << 1);
            #pragma unroll
            for (int k = 0; k < 4; k++) {
                int kk = k ^ sw;
                *reinterpret_cast<ulonglong2*>(tb + (kk << 2)) =
                    make_ulonglong2(tacc[2*k], tacc[2*k+1]);
            }
        }

        __syncthreads();   // Ts ready

        // ---- step4: accO += R[ci] * T[e][ci][o] ----
        {
            const float* tb = Ts + (f & 1) * 4096 + e * 256;
            #pragma unroll 4
            for (int c = 0; c < 8; c++) {
                float2 rp = *reinterpret_cast<float2*>(&accR[c]);
                const int cA = 2 * c, cB = 2 * c + 1;
                u64 rdA = dup2(rp.x);
                u64 rdB = dup2(rp.y);
                const float* ta = tb + cA * 16;
                const float* tc = tb + cB * 16;
                const int swA = (cA & 3) ^ ((e & 1) << 1);
                const int swB = (cB & 3) ^ ((e & 1) << 1);
                ulonglong2 a0 = *reinterpret_cast<const ulonglong2*>(ta + ((0 ^ swA) << 2));
                ulonglong2 a1 = *reinterpret_cast<const ulonglong2*>(ta + ((1 ^ swA) << 2));
                ulonglong2 a2 = *reinterpret_cast<const ulonglong2*>(ta + ((2 ^ swA) << 2));
                ulonglong2 a3 = *reinterpret_cast<const ulonglong2*>(ta + ((3 ^ swA) << 2));
                accO[0] = f2fma(rdA, a0.x, accO[0]);
                accO[1] = f2fma(rdA, a0.y, accO[1]);
                accO[2] = f2fma(rdA, a1.x, accO[2]);
                accO[3] = f2fma(rdA, a1.y, accO[3]);
                accO[4] = f2fma(rdA, a2.x, accO[4]);
                accO[5] = f2fma(rdA, a2.y, accO[5]);
                accO[6] = f2fma(rdA, a3.x, accO[6]);
                accO[7] = f2fma(rdA, a3.y, accO[7]);
                ulonglong2 b0 = *reinterpret_cast<const ulonglong2*>(tc + ((0 ^ swB) << 2));
                ulonglong2 b1 = *reinterpret_cast<const ulonglong2*>(tc + ((1 ^ swB) << 2));
                ulonglong2 b2 = *reinterpret_cast<const ulonglong2*>(tc + ((2 ^ swB) << 2));
                ulonglong2 b3 = *reinterpret_cast<const ulonglong2*>(tc + ((3 ^ swB) << 2));
                accO[0] = f2fma(rdB, b0.x, accO[0]);
                accO[1] = f2fma(rdB, b0.y, accO[1]);
                accO[2] = f2fma(rdB, b1.x, accO[2]);
                accO[3] = f2fma(rdB, b1.y, accO[3]);
                accO[4] = f2fma(rdB, b2.x, accO[4]);
                accO[5] = f2fma(rdB, b2.y, accO[5]);
                accO[6] = f2fma(rdB, b3.x, accO[6]);
                accO[7] = f2fma(rdB, b3.y, accO[7]);
            }
        }
    }

    // ---- epilogue: out[e][co][0..15] ----
    float* op = out + ((size_t)(e0 + e) * 16 + co) * 16;
    *reinterpret_cast<ulonglong2*>(op)      = make_ulonglong2(accO[0], accO[1]);
    *reinterpret_cast<ulonglong2*>(op + 4)  = make_ulonglong2(accO[2], accO[3]);
    *reinterpret_cast<ulonglong2*>(op + 8)  = make_ulonglong2(accO[4], accO[5]);
    *reinterpret_cast<ulonglong2*>(op + 12) = make_ulonglong2(accO[6], accO[7]);
}

// ---------------------------------------------------------------------------
extern "C" void kernel_launch(void* const* d_in, const int* in_sizes, int n_in,
                              void* d_out, int out_size)
{
    const float* features = (const float*)d_in[0];
    const float* inv      = (const float*)d_in[1];
    const float* basis    = (const float*)d_in[2];
    const float* w1  = (const float*)d_in[3];
    const float* b1  = (const float*)d_in[4];
    const float* g1  = (const float*)d_in[5];
    const float* be1 = (const float*)d_in[6];
    const float* w2  = (const float*)d_in[7];
    const float* b2  = (const float*)d_in[8];
    const float* g2  = (const float*)d_in[9];
    const float* be2 = (const float*)d_in[10];
    const float* w3  = (const float*)d_in[11];
    float* out = (float*)d_out;

    const int smem_bytes = (2 * BB_FLOATS + 2 * 4096 + 16 * 33 * 2) * 4;  // 70272
    cudaFuncSetAttribute(conv_main_kernel,
                         cudaFuncAttributeMaxDynamicSharedMemorySize, smem_bytes);

    w3t_kernel<<<(FREQ * 32 * 256 + 255) / 256, 256>>>(w3);
    mlp_kernel<<<E_TOT / 8, 256>>>(inv, w1, b1, g1, be1, w2, b2, g2, be2);
    conv_main_kernel<<<NBLK, 256, smem_bytes>>>(features, basis, out);
}

// round 7
// speedup vs baseline: 2.7978x; 2.7978x over previous
#include <cuda_runtime.h>
#include <cuda_bf16.h>

typedef unsigned long long u64;
typedef unsigned int u32;

#define E_TOT   10000
#define FREQ    44
#define EB      32
#define NBLK    ((E_TOT + EB - 1) / EB)   // 313
#define LN_EPS  1e-5f

#define MLP_BLOCKS  (E_TOT / 8)                    // 1250
#define W3T_BLOCKS  ((FREQ * 32 * 256 + 255) / 256) // 1408

// scratch
__device__ float g_h[E_TOT * 32];
__device__ float g_w3t[FREQ * 32 * 256];   // [f][m][p], p = ci*16+co

// ---------------------------------------------------------------------------
__device__ __forceinline__ u64 f2fma(u64 a, u64 b, u64 c) {
    u64 d;
    asm("fma.rn.f32x2 %0, %1, %2, %3;" : "=l"(d) : "l"(a), "l"(b), "l"(c));
    return d;
}
__device__ __forceinline__ u64 dup2(float x) {
    u64 d;
    asm("mov.b64 %0, {%1, %1};" : "=l"(d) : "f"(x));
    return d;
}
__device__ __forceinline__ ulonglong2 ldg2g(const float* p, bool v) {
    if (v) return *reinterpret_cast<const ulonglong2*>(p);
    return make_ulonglong2(0ull, 0ull);
}

// ---------------------------------------------------------------------------
// prep kernel: blockIdx < MLP_BLOCKS -> RadialProfile MLP (warp per edge)
//              else                  -> w3 transpose into g_w3t
// ---------------------------------------------------------------------------
__device__ __forceinline__ float ln_relu_32(float y, float gamma, float beta) {
    float s = y, q = y * y;
    #pragma unroll
    for (int d = 16; d > 0; d >>= 1) {
        s += __shfl_xor_sync(0xffffffffu, s, d);
        q += __shfl_xor_sync(0xffffffffu, q, d);
    }
    float mean = s * (1.0f / 32.0f);
    float var  = q * (1.0f / 32.0f) - mean * mean;
    float r = rsqrtf(var + LN_EPS);
    float v = (y - mean) * r * gamma + beta;
    return fmaxf(v, 0.0f);
}

__global__ void __launch_bounds__(256) prep_kernel(
    const float* __restrict__ inv,
    const float* __restrict__ w1, const float* __restrict__ b1,
    const float* __restrict__ g1, const float* __restrict__ be1,
    const float* __restrict__ w2, const float* __restrict__ b2,
    const float* __restrict__ g2, const float* __restrict__ be2,
    const float* __restrict__ w3)
{
    if (blockIdx.x >= MLP_BLOCKS) {
        int idx = (blockIdx.x - MLP_BLOCKS) * 256 + threadIdx.x;
        if (idx < FREQ * 32 * 256) {
            int p = idx & 255;
            int m = (idx >> 8) & 31;
            int f = idx >> 13;
            int row = (p & 15) * 704 + (p >> 4) * 44 + f;
            g_w3t[idx] = w3[row * 32 + m];
        }
        return;
    }

    __shared__ float w1_s[32 * 16];
    __shared__ float w2_s[32 * 32];
    __shared__ float p_s[6 * 32];

    int tid = threadIdx.x;
    for (int i = tid; i < 512;  i += 256) w1_s[i] = w1[i];
    for (int i = tid; i < 1024; i += 256) w2_s[i] = w2[i];
    if (tid < 32) {
        p_s[tid]       = b1[tid];
        p_s[32  + tid] = g1[tid];
        p_s[64  + tid] = be1[tid];
        p_s[96  + tid] = b2[tid];
        p_s[128 + tid] = g2[tid];
        p_s[160 + tid] = be2[tid];
    }
    __syncthreads();

    int w = tid >> 5;
    int m = tid & 31;
    int e = blockIdx.x * 8 + w;

    float xv = (m < 16) ? inv[e * 16 + m] : 0.0f;

    float y = p_s[m];
    #pragma unroll
    for (int in = 0; in < 16; in++)
        y = fmaf(__shfl_sync(0xffffffffu, xv, in), w1_s[m * 16 + in], y);
    y = ln_relu_32(y, p_s[32 + m], p_s[64 + m]);

    float y2 = p_s[96 + m];
    #pragma unroll
    for (int k = 0; k < 32; k++)
        y2 = fmaf(__shfl_sync(0xffffffffu, y, k), w2_s[m * 32 + k], y2);
    y2 = ln_relu_32(y2, p_s[128 + m], p_s[160 + m]);

    g_h[e * 32 + m] = y2;
}

// ---------------------------------------------------------------------------
// Kernel 2: fused conv, EB=32 edges / block, 256 threads. (round-4 structure;
// fs staging removed, features loaded direct; 3 blocks/SM target)
//
// smem:
//  Ts[e][256]  : T slice; o-chunk k at kk = k ^ ((ci>>1)&3) ^ ((e>>4)&1)<<1
//  Rs[e][264]  : R slice; column p stored at p ^ (e & 16)
//  hs[m][32]   : h transposed (pair loads along edges)
// ---------------------------------------------------------------------------
__global__ void __launch_bounds__(256, 3) conv_main_kernel(
    const float* __restrict__ features,  // [E,16,16]
    const float* __restrict__ basis,     // [E,16,44,16]
    float*       __restrict__ out)       // [E,16,16]
{
    extern __shared__ float sm[];
    float* Ts = sm;                  // 32*256 = 8192
    float* Rs = sm + 8192;           // 32*264 = 8448
    float* hs = sm + 16640;          // 32*32  = 1024  -> total 17664 floats

    const int t  = threadIdx.x;
    const int e0 = blockIdx.x * EB;

    // stage hs[m][e]
    #pragma unroll
    for (int i = 0; i < 4; i++) {
        int idx = t + i * 256;
        int m = idx >> 5, e = idx & 31;
        hs[m * 32 + e] = (e0 + e < E_TOT) ? g_h[(e0 + e) * 32 + m] : 0.0f;
    }

    // roles
    const int e2  = t >> 3;              // step2 edge
    const int ci0 = t & 7;               // step2 ci (and ci+8)
    const int et  = t >> 7;              // step3 e-tile (16 edges)
    const int p0  = (t & 127) * 2;       // step3 p pair
    const int w   = t >> 5;              // warp
    const int l   = t & 31;
    const int co  = l & 15;              // step4
    const int eh  = (l >> 4) << 4;       // step4 half offset (0 or 16)

    const bool v2 = (e0 + e2) < E_TOT;
    const float* basE = basis + (size_t)(e0 + e2) * 11264;

    // features rows (e2, ci0) and (e2, ci0+8) — loaded once; ptxas may spill
    // these under the 3-blocks/SM reg budget (cheap per-f reloads from local).
    float fA[16], fB[16];
    {
        const float4* pa = reinterpret_cast<const float4*>(features + ((size_t)(e0 + e2) * 16 + ci0) * 16);
        const float4* pb = reinterpret_cast<const float4*>(features + ((size_t)(e0 + e2) * 16 + ci0 + 8) * 16);
        #pragma unroll
        for (int k = 0; k < 4; k++) {
            float4 a = v2 ? pa[k] : make_float4(0.f, 0.f, 0.f, 0.f);
            float4 b = v2 ? pb[k] : make_float4(0.f, 0.f, 0.f, 0.f);
            fA[4*k] = a.x; fA[4*k+1] = a.y; fA[4*k+2] = a.z; fA[4*k+3] = a.w;
            fB[4*k] = b.x; fB[4*k+1] = b.y; fB[4*k+2] = b.z; fB[4*k+3] = b.w;
        }
    }

    u64 accO[2][8];
    #pragma unroll
    for (int r = 0; r < 2; r++)
        #pragma unroll
        for (int i = 0; i < 8; i++) accO[r][i] = 0ull;

    const int sw2  = (ci0 >> 1) & 3;
    const int swe2 = ((e2 >> 4) & 1) << 1;

    __syncthreads();

    for (int f = 0; f < FREQ; f++) {
        if (f) __syncthreads();   // prev step4 done with Ts/Rs

        // ================= step2: T rows (e2, ci0) and (e2, ci0+8) ==========
        {
            u64 tA[8], tB[8];
            #pragma unroll
            for (int i = 0; i < 8; i++) { tA[i] = 0ull; tB[i] = 0ull; }

            const float* bp = basE + f * 16;
            #pragma unroll 4
            for (int in = 0; in < 16; in++) {
                const float* q = bp + in * 704;
                ulonglong2 x0 = ldg2g(q,      v2);
                ulonglong2 x1 = ldg2g(q + 4,  v2);
                ulonglong2 x2 = ldg2g(q + 8,  v2);
                ulonglong2 x3 = ldg2g(q + 12, v2);
                u64 da = dup2(fA[in]);
                u64 db = dup2(fB[in]);
                tA[0] = f2fma(da, x0.x, tA[0]); tA[1] = f2fma(da, x0.y, tA[1]);
                tA[2] = f2fma(da, x1.x, tA[2]); tA[3] = f2fma(da, x1.y, tA[3]);
                tA[4] = f2fma(da, x2.x, tA[4]); tA[5] = f2fma(da, x2.y, tA[5]);
                tA[6] = f2fma(da, x3.x, tA[6]); tA[7] = f2fma(da, x3.y, tA[7]);
                tB[0] = f2fma(db, x0.x, tB[0]); tB[1] = f2fma(db, x0.y, tB[1]);
                tB[2] = f2fma(db, x1.x, tB[2]); tB[3] = f2fma(db, x1.y, tB[3]);
                tB[4] = f2fma(db, x2.x, tB[4]); tB[5] = f2fma(db, x2.y, tB[5]);
                tB[6] = f2fma(db, x3.x, tB[6]); tB[7] = f2fma(db, x3.y, tB[7]);
            }
            float* ta = Ts + e2 * 256 + ci0 * 16;
            float* tb = ta + 128;          // ci0 + 8
            #pragma unroll
            for (int k = 0; k < 4; k++) {
                int kk = k ^ sw2 ^ swe2;
                *reinterpret_cast<ulonglong2*>(ta + (kk << 2)) = make_ulonglong2(tA[2*k], tA[2*k+1]);
                *reinterpret_cast<ulonglong2*>(tb + (kk << 2)) = make_ulonglong2(tB[2*k], tB[2*k+1]);
            }
        }

        // ================= step3: R[16e][2p] from g_w3t ======================
        {
            u64 acc[8][2];
            #pragma unroll
            for (int i = 0; i < 8; i++) { acc[i][0] = 0ull; acc[i][1] = 0ull; }

            const float* wp = g_w3t + (size_t)f * 8192 + p0;
            const float* hp = hs + (et << 4);
            #pragma unroll 8
            for (int m = 0; m < 32; m++) {
                float2 wv = *reinterpret_cast<const float2*>(wp + m * 256);
                u64 w0 = dup2(wv.x);
                u64 w1 = dup2(wv.y);
                const u64* hq = reinterpret_cast<const u64*>(hp + m * 32);
                #pragma unroll
                for (int i = 0; i < 8; i++) {
                    u64 hv = hq[i];
                    acc[i][0] = f2fma(hv, w0, acc[i][0]);
                    acc[i][1] = f2fma(hv, w1, acc[i][1]);
                }
            }
            const int px = p0 ^ (et << 4);
            #pragma unroll
            for (int i = 0; i < 8; i++) {
                float2 a0 = *reinterpret_cast<float2*>(&acc[i][0]);
                float2 a1 = *reinterpret_cast<float2*>(&acc[i][1]);
                float* r0 = Rs + ((et << 4) + 2 * i) * 264 + px;
                float* r1 = r0 + 264;
                *reinterpret_cast<float2*>(r0) = make_float2(a0.x, a1.x);
                *reinterpret_cast<float2*>(r1) = make_float2(a0.y, a1.y);
            }
        }

        __syncthreads();   // Ts + Rs ready

        // ================= step4: out accum =================================
        #pragma unroll
        for (int r = 0; r < 2; r++) {
            const int e  = w + 8 * r + eh;
            const int ex = e & 16;
            const float* Re = Rs + e * 264;
            const float* Te = Ts + e * 256;
            const int swe = ((e >> 4) & 1) << 1;
            #pragma unroll 4
            for (int c = 0; c < 16; c++) {
                float rv = Re[(c * 16 + co) ^ ex];
                u64 rd = dup2(rv);
                const float* tc = Te + c * 16;
                const int sws = ((c >> 1) & 3) ^ swe;
                ulonglong2 x0 = *reinterpret_cast<const ulonglong2*>(tc + ((0 ^ sws) << 2));
                ulonglong2 x1 = *reinterpret_cast<const ulonglong2*>(tc + ((1 ^ sws) << 2));
                ulonglong2 x2 = *reinterpret_cast<const ulonglong2*>(tc + ((2 ^ sws) << 2));
                ulonglong2 x3 = *reinterpret_cast<const ulonglong2*>(tc + ((3 ^ sws) << 2));
                accO[r][0] = f2fma(rd, x0.x, accO[r][0]);
                accO[r][1] = f2fma(rd, x0.y, accO[r][1]);
                accO[r][2] = f2fma(rd, x1.x, accO[r][2]);
                accO[r][3] = f2fma(rd, x1.y, accO[r][3]);
                accO[r][4] = f2fma(rd, x2.x, accO[r][4]);
                accO[r][5] = f2fma(rd, x2.y, accO[r][5]);
                accO[r][6] = f2fma(rd, x3.x, accO[r][6]);
                accO[r][7] = f2fma(rd, x3.y, accO[r][7]);
            }
        }
    }

    // epilogue
    #pragma unroll
    for (int r = 0; r < 2; r++) {
        const int e = w + 8 * r + eh;
        if (e0 + e < E_TOT) {
            float* op = out + ((size_t)(e0 + e) * 16 + co) * 16;
            *reinterpret_cast<ulonglong2*>(op)      = make_ulonglong2(accO[r][0], accO[r][1]);
            *reinterpret_cast<ulonglong2*>(op + 4)  = make_ulonglong2(accO[r][2], accO[r][3]);
            *reinterpret_cast<ulonglong2*>(op + 8)  = make_ulonglong2(accO[r][4], accO[r][5]);
            *reinterpret_cast<ulonglong2*>(op + 12) = make_ulonglong2(accO[r][6], accO[r][7]);
        }
    }
}

// ---------------------------------------------------------------------------
extern "C" void kernel_launch(void* const* d_in, const int* in_sizes, int n_in,
                              void* d_out, int out_size)
{
    const float* features = (const float*)d_in[0];
    const float* inv      = (const float*)d_in[1];
    const float* basis    = (const float*)d_in[2];
    const float* w1  = (const float*)d_in[3];
    const float* b1  = (const float*)d_in[4];
    const float* g1  = (const float*)d_in[5];
    const float* be1 = (const float*)d_in[6];
    const float* w2  = (const float*)d_in[7];
    const float* b2  = (const float*)d_in[8];
    const float* g2  = (const float*)d_in[9];
    const float* be2 = (const float*)d_in[10];
    const float* w3  = (const float*)d_in[11];
    float* out = (float*)d_out;

    const int smem_bytes = 17664 * 4;   // 70656
    cudaFuncSetAttribute(conv_main_kernel,
                         cudaFuncAttributeMaxDynamicSharedMemorySize, smem_bytes);

    prep_kernel<<<MLP_BLOCKS + W3T_BLOCKS, 256>>>(inv, w1, b1, g1, be1,
                                                  w2, b2, g2, be2, w3);
    conv_main_kernel<<<NBLK, 256, smem_bytes>>>(features, basis, out);
}